// round 9
// baseline (speedup 1.0000x reference)
#include <cuda_runtime.h>

// BWSGODE: 8192-step serial scalar ODE, single-thread issue-bound.
//
// v9 = v7 (best, 120.9us; bit-exact producer + SMSP-0-isolated consumers,
// uniform 512-row chunk publishing) with the per-iter trajectory store
// split STS.128 -> 2 x st.shared.v2.f32 (forced via inline asm).
// Hypothesis under test: the measured 28 cyc/iter is 12 fma-pipe ops x 2
// (FADDs riding the alu pipe) + ~4 cyc of wide-store dispatch; if so, two
// 64-bit stores cost fewer issue slots than one 128-bit store and the loop
// drops toward its 24-cyc fp floor. If 28 = 14x2 with the store free, this
// is neutral and v7 is the confirmed floor.
// v8's fine-grained tail publishing reverted (measured neutral/negative).

#define CHUNK_LOG2 9
#define CHUNK (1 << CHUNK_LOG2)

__shared__ volatile int s_progress;

__device__ __forceinline__ void sts_v2(unsigned saddr, float x, float y) {
    asm volatile("st.shared.v2.f32 [%0], {%1, %2};"
                 :: "r"(saddr), "f"(x), "f"(y));
}

__global__ void __launch_bounds__(256, 1)
bwsg_ode_kernel(const float* __restrict__ y0,
                const float* __restrict__ p,
                float* __restrict__ out,
                int num_steps) {
    extern __shared__ float4 traj[];  // num_steps entries (128 KB @ 8192)

    const int tid = threadIdx.x;
    const int wid = tid >> 5;
    if (tid == 0) s_progress = 0;
    __syncthreads();  // the ONLY block-wide sync; everything after is P/C.

    const float iv = __ldg(&y0[4]);

    if (tid == 0) {
        // ---------------- producer: the serial recurrence ----------------
        float B = __ldg(&y0[0]);
        float W = __ldg(&y0[1]);
        float S = __ldg(&y0[2]);
        float G = __ldg(&y0[3]);

        const float p0 = p[0], p2 = p[2], p5 = p[5], p8 = p[8];
        const float np1 = -p[1], np3 = -p[3], np4 = -p[4];
        const float np6 = -p[6], np7 = -p[7], np9 = -p[9];
        const float np0 = -p0;

        const float fi  = (iv != 0.0f) ? 1.0f : 0.0f;
        const float thr = __fsub_rn(__fadd_rn(5.0f, iv), 1.0f);

        // First integer step with mask==1 (j >= thr <=> j >= ceil(thr) for
        // integer j; fp compare of exact integers is exact).
        int j0 = 1;
        if (fi != 0.0f) {
            float ct = ceilf(thr);
            if (ct > 1.0f) {
                j0 = (ct >= (float)num_steps) ? num_steps : (int)ct;
            }
        }

        const unsigned sbase =
            (unsigned)__cvta_generic_to_shared((void*)traj);

        sts_v2(sbase +  0, B, W);
        sts_v2(sbase +  8, S, G);

        // ---- Phase 1: mask == 0 (interventional only), B frozen ----
        for (int j = 1; j < j0; ++j) {
            float a = __fmaf_rn(np0, G, p0);
            a       = __fmaf_rn(np1, S, a);
            float c = __fmaf_rn(p2, G, np4);
            float b = __fmaf_rn(np3, W, c);
            float d = __fmaf_rn(p5, S, np7);
            float e = __fmul_rn(W, d);
            float nS = __fmaf_rn(b, S, S);
            float nW = __fmaf_rn(e, W, W);
            float nG = __fmaf_rn(a, G, G);
            W = nW; S = nS; G = nG;
            const unsigned sa = sbase + ((unsigned)j << 4);
            sts_v2(sa,     B, W);
            sts_v2(sa + 8, S, G);
        }

        // ---- Phase 2: mask == 1 hot loop (14 fp ops), chunk-published ----
        int j = j0;
        while (j < num_steps) {
            const int end = min((((j >> CHUNK_LOG2) + 1) << CHUNK_LOG2),
                                num_steps);
            #pragma unroll 8
            for (; j < end; ++j) {
                float a = __fmaf_rn(np0, G, p0);     // p0 - p0*G
                a       = __fmaf_rn(np1, S, a);      //   - p1*S
                float t = __fadd_rn(W, B);           // W + B
                float c = __fmaf_rn(p2, G, np4);     // p2*G - p4
                float b = __fmaf_rn(np3, t, c);      //   - p3*(W+B)
                float d = __fmaf_rn(p5, S, np7);     // p5*S - p7
                d       = __fmaf_rn(np6, B, d);      //   - p6*B
                float e = __fmul_rn(W, d);           // W*(...)
                float f = __fadd_rn(S, W);           // S + W
                float g = __fmaf_rn(p8, f, np9);     // p8*(S+W) - p9
                float nB = __fmaf_rn(g, B, B);
                float nW = __fmaf_rn(e, W, W);
                float nS = __fmaf_rn(b, S, S);
                float nG = __fmaf_rn(a, G, G);
                B = nB; W = nW; S = nS; G = nG;
                const unsigned sa = sbase + ((unsigned)j << 4);
                sts_v2(sa,     B, W);                // STS.64 x2 (probe)
                sts_v2(sa + 8, S, G);
            }
            __threadfence_block();
            s_progress = end;
        }
        __threadfence_block();
        s_progress = num_steps;  // covers j0 == num_steps
    } else if (wid != 4 && tid >= 32) {
        // ------- consumers: warps 1,2,3,5,6,7 (SMSP 0 kept clear) --------
        const int ct  = (wid < 4) ? (tid - 32) : (tid - 64);  // 0..191
        const int ncs = 192;
        const float* tf = (const float*)traj;       // flat smem floats
        float4* o4 = (float4*)out;

        const int total_f  = num_steps * 5;
        const int total_f4 = total_f >> 2;
        const int n_chunks = (num_steps + CHUNK - 1) >> CHUNK_LOG2;
        const int f4_per_chunk = (CHUNK * 5) >> 2;  // 640

        for (int k = 0; k < n_chunks; ++k) {
            const int rows_done = min((k + 1) << CHUNK_LOG2, num_steps);
            while (s_progress < rows_done) __nanosleep(256);
            __threadfence_block();  // acquire: traj data before flag

            const int m0 = k * f4_per_chunk;
            const int m1 = min(m0 + f4_per_chunk, total_f4);
            for (int m = m0 + ct; m < m1; m += ncs) {
                const int n = m << 2;
                float v[4];
                #pragma unroll
                for (int e = 0; e < 4; ++e) {
                    const int ne = n + e;
                    const int r  = ne / 5;
                    const int c  = ne - r * 5;
                    v[e] = (c == 4) ? iv : tf[(r << 2) + c];
                }
                o4[m] = make_float4(v[0], v[1], v[2], v[3]);  // STG.128
            }
        }
        // scalar tail if num_steps*5 % 4 != 0 (not hit at 8192, kept general)
        if (ct == 0) {
            for (int ne = total_f4 << 2; ne < total_f; ++ne) {
                const int r = ne / 5;
                const int c = ne - r * 5;
                out[ne] = (c == 4) ? iv : tf[(r << 2) + c];
            }
        }
    }
    // warp 0 lanes 1..31 and all of warp 4: fall through and exit,
    // leaving SMSP 0's issue slots to the producer.
}

extern "C" void kernel_launch(void* const* d_in, const int* in_sizes, int n_in,
                              void* d_out, int out_size) {
    const float* y0     = (const float*)d_in[0];
    const float* params = (const float*)d_in[1];
    const int num_steps = out_size / 5;

    const size_t smem = (size_t)num_steps * sizeof(float4);
    cudaFuncSetAttribute(bwsg_ode_kernel,
                         cudaFuncAttributeMaxDynamicSharedMemorySize,
                         (int)smem);
    bwsg_ode_kernel<<<1, 256, smem>>>(y0, params, (float*)d_out, num_steps);
}

// round 10
// speedup vs baseline: 1.0024x; 1.0024x over previous
#include <cuda_runtime.h>

// BWSGODE: 8192-step serial scalar ODE, single-thread issue-bound.
//
// v10 = v7 (best; bit-exact producer + SMSP-0-isolated consumers) with the
// producer's publish path lightened:
//   - __threadfence_block + volatile store  ->  one st.release.cta.shared
//     (one-sided release; avoids MEMBAR.ALL.CTA's 36 + k*n_STS_in_flight
//     drain on the serial critical path)
//   - consumer poll: volatile read -> ld.acquire.cta.shared
//   - CHUNK 512 -> 1024 (half the publishes; consumer copy of a chunk is
//     ~2us vs the producer's ~15us per chunk, so the tail stays hidden)
// Loop floor re-certified in r9: 14 fma-pipe ops x rt=2 = 28 cyc/iter;
// 8191*28 @ 1.92GHz = 119.4us ~= measured kernel time. This targets the
// only unproven producer-side cost (the 16 fences).

#define CHUNK_LOG2 10
#define CHUNK (1 << CHUNK_LOG2)

__shared__ int s_progress;

__device__ __forceinline__ void publish(unsigned paddr, int v) {
    asm volatile("st.release.cta.shared.u32 [%0], %1;"
                 :: "r"(paddr), "r"(v) : "memory");
}
__device__ __forceinline__ int poll(unsigned paddr) {
    int v;
    asm volatile("ld.acquire.cta.shared.u32 %0, [%1];"
                 : "=r"(v) : "r"(paddr) : "memory");
    return v;
}

__global__ void __launch_bounds__(256, 1)
bwsg_ode_kernel(const float* __restrict__ y0,
                const float* __restrict__ p,
                float* __restrict__ out,
                int num_steps) {
    extern __shared__ float4 traj[];  // num_steps entries (128 KB @ 8192)

    const int tid = threadIdx.x;
    const int wid = tid >> 5;
    const unsigned paddr =
        (unsigned)__cvta_generic_to_shared((void*)&s_progress);
    if (tid == 0) s_progress = 0;
    __syncthreads();  // the ONLY block-wide sync; everything after is P/C.

    const float iv = __ldg(&y0[4]);

    if (tid == 0) {
        // ---------------- producer: the serial recurrence ----------------
        float B = __ldg(&y0[0]);
        float W = __ldg(&y0[1]);
        float S = __ldg(&y0[2]);
        float G = __ldg(&y0[3]);

        const float p0 = p[0], p2 = p[2], p5 = p[5], p8 = p[8];
        const float np1 = -p[1], np3 = -p[3], np4 = -p[4];
        const float np6 = -p[6], np7 = -p[7], np9 = -p[9];
        const float np0 = -p0;

        const float fi  = (iv != 0.0f) ? 1.0f : 0.0f;
        const float thr = __fsub_rn(__fadd_rn(5.0f, iv), 1.0f);

        // First integer step with mask==1 (j >= thr <=> j >= ceil(thr) for
        // integer j; fp compare of exact integers is exact).
        int j0 = 1;
        if (fi != 0.0f) {
            float ct = ceilf(thr);
            if (ct > 1.0f) {
                j0 = (ct >= (float)num_steps) ? num_steps : (int)ct;
            }
        }

        traj[0] = make_float4(B, W, S, G);

        // ---- Phase 1: mask == 0 (interventional only), B frozen ----
        for (int j = 1; j < j0; ++j) {
            float a = __fmaf_rn(np0, G, p0);
            a       = __fmaf_rn(np1, S, a);
            float c = __fmaf_rn(p2, G, np4);
            float b = __fmaf_rn(np3, W, c);
            float d = __fmaf_rn(p5, S, np7);
            float e = __fmul_rn(W, d);
            float nS = __fmaf_rn(b, S, S);
            float nW = __fmaf_rn(e, W, W);
            float nG = __fmaf_rn(a, G, G);
            W = nW; S = nS; G = nG;
            traj[j] = make_float4(B, W, S, G);
        }

        // ---- Phase 2: mask == 1 hot loop (14 fp ops), chunk-published ----
        int j = j0;
        while (j < num_steps) {
            const int end = min((((j >> CHUNK_LOG2) + 1) << CHUNK_LOG2),
                                num_steps);
            #pragma unroll 8
            for (; j < end; ++j) {
                float a = __fmaf_rn(np0, G, p0);     // p0 - p0*G
                a       = __fmaf_rn(np1, S, a);      //   - p1*S
                float t = __fadd_rn(W, B);           // W + B
                float c = __fmaf_rn(p2, G, np4);     // p2*G - p4
                float b = __fmaf_rn(np3, t, c);      //   - p3*(W+B)
                float d = __fmaf_rn(p5, S, np7);     // p5*S - p7
                d       = __fmaf_rn(np6, B, d);      //   - p6*B
                float e = __fmul_rn(W, d);           // W*(...)
                float f = __fadd_rn(S, W);           // S + W
                float g = __fmaf_rn(p8, f, np9);     // p8*(S+W) - p9
                float nB = __fmaf_rn(g, B, B);
                float nW = __fmaf_rn(e, W, W);
                float nS = __fmaf_rn(b, S, S);
                float nG = __fmaf_rn(a, G, G);
                B = nB; W = nW; S = nS; G = nG;
                traj[j] = make_float4(B, W, S, G);   // STS.128 (hidden)
            }
            publish(paddr, end);                      // release store
        }
        publish(paddr, num_steps);  // covers j0 == num_steps
    } else if (wid != 4 && tid >= 32) {
        // ------- consumers: warps 1,2,3,5,6,7 (SMSP 0 kept clear) --------
        const int ct  = (wid < 4) ? (tid - 32) : (tid - 64);  // 0..191
        const int ncs = 192;
        const float* tf = (const float*)traj;       // flat smem floats
        float4* o4 = (float4*)out;

        const int total_f  = num_steps * 5;
        const int total_f4 = total_f >> 2;
        const int n_chunks = (num_steps + CHUNK - 1) >> CHUNK_LOG2;
        const int f4_per_chunk = (CHUNK * 5) >> 2;  // 1280

        for (int k = 0; k < n_chunks; ++k) {
            const int rows_done = min((k + 1) << CHUNK_LOG2, num_steps);
            while (poll(paddr) < rows_done) __nanosleep(256);
            // acquire load orders traj reads after the flag.

            const int m0 = k * f4_per_chunk;
            const int m1 = min(m0 + f4_per_chunk, total_f4);
            for (int m = m0 + ct; m < m1; m += ncs) {
                const int n = m << 2;
                float v[4];
                #pragma unroll
                for (int e = 0; e < 4; ++e) {
                    const int ne = n + e;
                    const int r  = ne / 5;
                    const int c  = ne - r * 5;
                    v[e] = (c == 4) ? iv : tf[(r << 2) + c];
                }
                o4[m] = make_float4(v[0], v[1], v[2], v[3]);  // STG.128
            }
        }
        // scalar tail if num_steps*5 % 4 != 0 (not hit at 8192, kept general)
        if (ct == 0) {
            for (int ne = total_f4 << 2; ne < total_f; ++ne) {
                const int r = ne / 5;
                const int c = ne - r * 5;
                out[ne] = (c == 4) ? iv : tf[(r << 2) + c];
            }
        }
    }
    // warp 0 lanes 1..31 and all of warp 4: fall through and exit,
    // leaving SMSP 0's issue slots to the producer.
}

extern "C" void kernel_launch(void* const* d_in, const int* in_sizes, int n_in,
                              void* d_out, int out_size) {
    const float* y0     = (const float*)d_in[0];
    const float* params = (const float*)d_in[1];
    const int num_steps = out_size / 5;

    const size_t smem = (size_t)num_steps * sizeof(float4);
    cudaFuncSetAttribute(bwsg_ode_kernel,
                         cudaFuncAttributeMaxDynamicSharedMemorySize,
                         (int)smem);
    bwsg_ode_kernel<<<1, 256, smem>>>(y0, params, (float*)d_out, num_steps);
}

// round 11
// speedup vs baseline: 1.0549x; 1.0524x over previous
#include <cuda_runtime.h>

// BWSGODE: 8192-step serial scalar ODE — certified issue-floor kernel.
//
// v11 = v7 (best measured: 120.9us bench / 119.7us kernel) + unroll 16.
// Floor analysis (rounds 2-10): the recurrence needs 14 fma-pipe fp32 ops
// per step (affine multipliers with 3+4+3+3 terms + 4 update FMAs,
// irreducible); one warp's SMSP fma port accepts 1 op / 2 cyc -> 28
// cyc/iter. 8191 x 28 / 1.92GHz = 119.4us = measured kernel time.
// Killed alternatives: f32x2 (r3/r4), FFMA-imm (r5), store split (r9),
// release/acquire publish (r10), fp64-pipe offload (latency), lane-split /
// helper-warp (SHFL/LDS in the carried chain), fp16 (precision).
// Structure: thread 0 runs the loop, publishes 512-row chunks via
// fence+volatile store; warps 1,2,3,5,6,7 stream chunks to global as
// STG.128 (warp 4 exits to keep SMSP 0 producer-only).

#define CHUNK_LOG2 9
#define CHUNK (1 << CHUNK_LOG2)

__shared__ volatile int s_progress;

__global__ void __launch_bounds__(256, 1)
bwsg_ode_kernel(const float* __restrict__ y0,
                const float* __restrict__ p,
                float* __restrict__ out,
                int num_steps) {
    extern __shared__ float4 traj[];  // num_steps entries (128 KB @ 8192)

    const int tid = threadIdx.x;
    const int wid = tid >> 5;
    if (tid == 0) s_progress = 0;
    __syncthreads();  // the ONLY block-wide sync; everything after is P/C.

    const float iv = __ldg(&y0[4]);

    if (tid == 0) {
        // ---------------- producer: the serial recurrence ----------------
        float B = __ldg(&y0[0]);
        float W = __ldg(&y0[1]);
        float S = __ldg(&y0[2]);
        float G = __ldg(&y0[3]);

        const float p0 = p[0], p2 = p[2], p5 = p[5], p8 = p[8];
        const float np1 = -p[1], np3 = -p[3], np4 = -p[4];
        const float np6 = -p[6], np7 = -p[7], np9 = -p[9];
        const float np0 = -p0;

        const float fi  = (iv != 0.0f) ? 1.0f : 0.0f;
        const float thr = __fsub_rn(__fadd_rn(5.0f, iv), 1.0f);

        // First integer step with mask==1 (j >= thr <=> j >= ceil(thr) for
        // integer j; fp compare of exact integers is exact).
        int j0 = 1;
        if (fi != 0.0f) {
            float ct = ceilf(thr);
            if (ct > 1.0f) {
                j0 = (ct >= (float)num_steps) ? num_steps : (int)ct;
            }
        }

        traj[0] = make_float4(B, W, S, G);

        // ---- Phase 1: mask == 0 (interventional only), B frozen ----
        for (int j = 1; j < j0; ++j) {
            float a = __fmaf_rn(np0, G, p0);
            a       = __fmaf_rn(np1, S, a);
            float c = __fmaf_rn(p2, G, np4);
            float b = __fmaf_rn(np3, W, c);
            float d = __fmaf_rn(p5, S, np7);
            float e = __fmul_rn(W, d);
            float nS = __fmaf_rn(b, S, S);
            float nW = __fmaf_rn(e, W, W);
            float nG = __fmaf_rn(a, G, G);
            W = nW; S = nS; G = nG;
            traj[j] = make_float4(B, W, S, G);
        }

        // ---- Phase 2: mask == 1 hot loop (14 fp ops), chunk-published ----
        int j = j0;
        while (j < num_steps) {
            const int end = min((((j >> CHUNK_LOG2) + 1) << CHUNK_LOG2),
                                num_steps);
            #pragma unroll 16
            for (; j < end; ++j) {
                float a = __fmaf_rn(np0, G, p0);     // p0 - p0*G
                a       = __fmaf_rn(np1, S, a);      //   - p1*S
                float t = __fadd_rn(W, B);           // W + B
                float c = __fmaf_rn(p2, G, np4);     // p2*G - p4
                float b = __fmaf_rn(np3, t, c);      //   - p3*(W+B)
                float d = __fmaf_rn(p5, S, np7);     // p5*S - p7
                d       = __fmaf_rn(np6, B, d);      //   - p6*B
                float e = __fmul_rn(W, d);           // W*(...)
                float f = __fadd_rn(S, W);           // S + W
                float g = __fmaf_rn(p8, f, np9);     // p8*(S+W) - p9
                float nB = __fmaf_rn(g, B, B);
                float nW = __fmaf_rn(e, W, W);
                float nS = __fmaf_rn(b, S, S);
                float nG = __fmaf_rn(a, G, G);
                B = nB; W = nW; S = nS; G = nG;
                traj[j] = make_float4(B, W, S, G);   // STS.128 (hidden)
            }
            __threadfence_block();
            s_progress = end;
        }
        __threadfence_block();
        s_progress = num_steps;  // covers j0 == num_steps
    } else if (wid != 4 && tid >= 32) {
        // ------- consumers: warps 1,2,3,5,6,7 (SMSP 0 kept clear) --------
        const int ct  = (wid < 4) ? (tid - 32) : (tid - 64);  // 0..191
        const int ncs = 192;
        const float* tf = (const float*)traj;       // flat smem floats
        float4* o4 = (float4*)out;

        const int total_f  = num_steps * 5;
        const int total_f4 = total_f >> 2;
        const int n_chunks = (num_steps + CHUNK - 1) >> CHUNK_LOG2;
        const int f4_per_chunk = (CHUNK * 5) >> 2;  // 640

        for (int k = 0; k < n_chunks; ++k) {
            const int rows_done = min((k + 1) << CHUNK_LOG2, num_steps);
            while (s_progress < rows_done) __nanosleep(256);
            __threadfence_block();  // acquire: traj data before flag

            const int m0 = k * f4_per_chunk;
            const int m1 = min(m0 + f4_per_chunk, total_f4);
            for (int m = m0 + ct; m < m1; m += ncs) {
                const int n = m << 2;
                float v[4];
                #pragma unroll
                for (int e = 0; e < 4; ++e) {
                    const int ne = n + e;
                    const int r  = ne / 5;
                    const int c  = ne - r * 5;
                    v[e] = (c == 4) ? iv : tf[(r << 2) + c];
                }
                o4[m] = make_float4(v[0], v[1], v[2], v[3]);  // STG.128
            }
        }
        // scalar tail if num_steps*5 % 4 != 0 (not hit at 8192, kept general)
        if (ct == 0) {
            for (int ne = total_f4 << 2; ne < total_f; ++ne) {
                const int r = ne / 5;
                const int c = ne - r * 5;
                out[ne] = (c == 4) ? iv : tf[(r << 2) + c];
            }
        }
    }
    // warp 0 lanes 1..31 and all of warp 4: fall through and exit,
    // leaving SMSP 0's issue slots to the producer.
}

extern "C" void kernel_launch(void* const* d_in, const int* in_sizes, int n_in,
                              void* d_out, int out_size) {
    const float* y0     = (const float*)d_in[0];
    const float* params = (const float*)d_in[1];
    const int num_steps = out_size / 5;

    const size_t smem = (size_t)num_steps * sizeof(float4);
    cudaFuncSetAttribute(bwsg_ode_kernel,
                         cudaFuncAttributeMaxDynamicSharedMemorySize,
                         (int)smem);
    bwsg_ode_kernel<<<1, 256, smem>>>(y0, params, (float*)d_out, num_steps);
}

// round 12
// speedup vs baseline: 1.1529x; 1.0929x over previous
#include <cuda_runtime.h>

// BWSGODE: 8192-step serial scalar ODE — issue-bound single-thread loop.
//
// v12 = v11 (best, 114.8us) with hot-loop unroll 16 -> 32.
// r11 falsified "bookkeeping is free": unroll 8->16 cut 5.4us, i.e. the
// per-iter IADD/ISETP/BRA/addr-add consume real issue slots on the single
// warp's scheduler. Unroll 32 halves the residue again and lets ptxas emit
// all 32 STS.128 as immediate offsets off one base register. Body ~7.7KB
// overflows L0 I$ (~6KB) but fits L1.5 (32KB); L0 miss ~+0.013cyc/instr,
// far below the ~0.3cyc/iter bookkeeping saving.
// Everything else identical to v11: thread 0 produces into shared traj and
// publishes 512-row chunks (fence + volatile store); warps 1,2,3,5,6,7
// stream chunks to global as STG.128; warp 4 exits so SMSP 0 belongs to
// the producer alone (hi-wid-first arbiter, r7: -4.2us).

#define CHUNK_LOG2 9
#define CHUNK (1 << CHUNK_LOG2)

__shared__ volatile int s_progress;

__global__ void __launch_bounds__(256, 1)
bwsg_ode_kernel(const float* __restrict__ y0,
                const float* __restrict__ p,
                float* __restrict__ out,
                int num_steps) {
    extern __shared__ float4 traj[];  // num_steps entries (128 KB @ 8192)

    const int tid = threadIdx.x;
    const int wid = tid >> 5;
    if (tid == 0) s_progress = 0;
    __syncthreads();  // the ONLY block-wide sync; everything after is P/C.

    const float iv = __ldg(&y0[4]);

    if (tid == 0) {
        // ---------------- producer: the serial recurrence ----------------
        float B = __ldg(&y0[0]);
        float W = __ldg(&y0[1]);
        float S = __ldg(&y0[2]);
        float G = __ldg(&y0[3]);

        const float p0 = p[0], p2 = p[2], p5 = p[5], p8 = p[8];
        const float np1 = -p[1], np3 = -p[3], np4 = -p[4];
        const float np6 = -p[6], np7 = -p[7], np9 = -p[9];
        const float np0 = -p0;

        const float fi  = (iv != 0.0f) ? 1.0f : 0.0f;
        const float thr = __fsub_rn(__fadd_rn(5.0f, iv), 1.0f);

        // First integer step with mask==1 (j >= thr <=> j >= ceil(thr) for
        // integer j; fp compare of exact integers is exact).
        int j0 = 1;
        if (fi != 0.0f) {
            float ct = ceilf(thr);
            if (ct > 1.0f) {
                j0 = (ct >= (float)num_steps) ? num_steps : (int)ct;
            }
        }

        traj[0] = make_float4(B, W, S, G);

        // ---- Phase 1: mask == 0 (interventional only), B frozen ----
        for (int j = 1; j < j0; ++j) {
            float a = __fmaf_rn(np0, G, p0);
            a       = __fmaf_rn(np1, S, a);
            float c = __fmaf_rn(p2, G, np4);
            float b = __fmaf_rn(np3, W, c);
            float d = __fmaf_rn(p5, S, np7);
            float e = __fmul_rn(W, d);
            float nS = __fmaf_rn(b, S, S);
            float nW = __fmaf_rn(e, W, W);
            float nG = __fmaf_rn(a, G, G);
            W = nW; S = nS; G = nG;
            traj[j] = make_float4(B, W, S, G);
        }

        // ---- Phase 2: mask == 1 hot loop (14 fp ops), chunk-published ----
        int j = j0;
        while (j < num_steps) {
            const int end = min((((j >> CHUNK_LOG2) + 1) << CHUNK_LOG2),
                                num_steps);
            #pragma unroll 32
            for (; j < end; ++j) {
                float a = __fmaf_rn(np0, G, p0);     // p0 - p0*G
                a       = __fmaf_rn(np1, S, a);      //   - p1*S
                float t = __fadd_rn(W, B);           // W + B
                float c = __fmaf_rn(p2, G, np4);     // p2*G - p4
                float b = __fmaf_rn(np3, t, c);      //   - p3*(W+B)
                float d = __fmaf_rn(p5, S, np7);     // p5*S - p7
                d       = __fmaf_rn(np6, B, d);      //   - p6*B
                float e = __fmul_rn(W, d);           // W*(...)
                float f = __fadd_rn(S, W);           // S + W
                float g = __fmaf_rn(p8, f, np9);     // p8*(S+W) - p9
                float nB = __fmaf_rn(g, B, B);
                float nW = __fmaf_rn(e, W, W);
                float nS = __fmaf_rn(b, S, S);
                float nG = __fmaf_rn(a, G, G);
                B = nB; W = nW; S = nS; G = nG;
                traj[j] = make_float4(B, W, S, G);   // STS.128 (imm offset)
            }
            __threadfence_block();
            s_progress = end;
        }
        __threadfence_block();
        s_progress = num_steps;  // covers j0 == num_steps
    } else if (wid != 4 && tid >= 32) {
        // ------- consumers: warps 1,2,3,5,6,7 (SMSP 0 kept clear) --------
        const int ct  = (wid < 4) ? (tid - 32) : (tid - 64);  // 0..191
        const int ncs = 192;
        const float* tf = (const float*)traj;       // flat smem floats
        float4* o4 = (float4*)out;

        const int total_f  = num_steps * 5;
        const int total_f4 = total_f >> 2;
        const int n_chunks = (num_steps + CHUNK - 1) >> CHUNK_LOG2;
        const int f4_per_chunk = (CHUNK * 5) >> 2;  // 640

        for (int k = 0; k < n_chunks; ++k) {
            const int rows_done = min((k + 1) << CHUNK_LOG2, num_steps);
            while (s_progress < rows_done) __nanosleep(256);
            __threadfence_block();  // acquire: traj data before flag

            const int m0 = k * f4_per_chunk;
            const int m1 = min(m0 + f4_per_chunk, total_f4);
            for (int m = m0 + ct; m < m1; m += ncs) {
                const int n = m << 2;
                float v[4];
                #pragma unroll
                for (int e = 0; e < 4; ++e) {
                    const int ne = n + e;
                    const int r  = ne / 5;
                    const int c  = ne - r * 5;
                    v[e] = (c == 4) ? iv : tf[(r << 2) + c];
                }
                o4[m] = make_float4(v[0], v[1], v[2], v[3]);  // STG.128
            }
        }
        // scalar tail if num_steps*5 % 4 != 0 (not hit at 8192, kept general)
        if (ct == 0) {
            for (int ne = total_f4 << 2; ne < total_f; ++ne) {
                const int r = ne / 5;
                const int c = ne - r * 5;
                out[ne] = (c == 4) ? iv : tf[(r << 2) + c];
            }
        }
    }
    // warp 0 lanes 1..31 and all of warp 4: fall through and exit,
    // leaving SMSP 0's issue slots to the producer.
}

extern "C" void kernel_launch(void* const* d_in, const int* in_sizes, int n_in,
                              void* d_out, int out_size) {
    const float* y0     = (const float*)d_in[0];
    const float* params = (const float*)d_in[1];
    const int num_steps = out_size / 5;

    const size_t smem = (size_t)num_steps * sizeof(float4);
    cudaFuncSetAttribute(bwsg_ode_kernel,
                         cudaFuncAttributeMaxDynamicSharedMemorySize,
                         (int)smem);
    bwsg_ode_kernel<<<1, 256, smem>>>(y0, params, (float*)d_out, num_steps);
}

// round 13
// speedup vs baseline: 1.1828x; 1.0259x over previous
#include <cuda_runtime.h>

// BWSGODE: 8192-step serial scalar ODE — issue-bound single-thread loop.
//
// v13 = v12 (best, 105.1us) with hot-loop unroll 32 -> 64.
// Model (revised r12): the 2 FADDs (W+B, S+W) issue on the ALU pipe, so
// the fma-port floor is 12 ops x rt2 = 24 cyc/iter; measured 24.9. The
// remaining ~0.9 cyc/iter is taken-BRA (~10cyc per unrolled block) +
// chunk bookkeeping; unroll 64 halves that share. Body ~15KB SASS fits
// L1.5 I$ (32KB; ~+0.015 cyc/instr miss cost, negligible).
// Structure (locked since r7/r12): thread 0 produces into shared traj,
// publishes 512-row chunks via fence+volatile store; warps 1,2,3,5,6,7
// stream chunks to global as STG.128; warp 4 exits so SMSP 0 belongs to
// the producer alone (hi-wid-first arbiter).

#define CHUNK_LOG2 9
#define CHUNK (1 << CHUNK_LOG2)

__shared__ volatile int s_progress;

__global__ void __launch_bounds__(256, 1)
bwsg_ode_kernel(const float* __restrict__ y0,
                const float* __restrict__ p,
                float* __restrict__ out,
                int num_steps) {
    extern __shared__ float4 traj[];  // num_steps entries (128 KB @ 8192)

    const int tid = threadIdx.x;
    const int wid = tid >> 5;
    if (tid == 0) s_progress = 0;
    __syncthreads();  // the ONLY block-wide sync; everything after is P/C.

    const float iv = __ldg(&y0[4]);

    if (tid == 0) {
        // ---------------- producer: the serial recurrence ----------------
        float B = __ldg(&y0[0]);
        float W = __ldg(&y0[1]);
        float S = __ldg(&y0[2]);
        float G = __ldg(&y0[3]);

        const float p0 = p[0], p2 = p[2], p5 = p[5], p8 = p[8];
        const float np1 = -p[1], np3 = -p[3], np4 = -p[4];
        const float np6 = -p[6], np7 = -p[7], np9 = -p[9];
        const float np0 = -p0;

        const float fi  = (iv != 0.0f) ? 1.0f : 0.0f;
        const float thr = __fsub_rn(__fadd_rn(5.0f, iv), 1.0f);

        // First integer step with mask==1 (j >= thr <=> j >= ceil(thr) for
        // integer j; fp compare of exact integers is exact).
        int j0 = 1;
        if (fi != 0.0f) {
            float ct = ceilf(thr);
            if (ct > 1.0f) {
                j0 = (ct >= (float)num_steps) ? num_steps : (int)ct;
            }
        }

        traj[0] = make_float4(B, W, S, G);

        // ---- Phase 1: mask == 0 (interventional only), B frozen ----
        for (int j = 1; j < j0; ++j) {
            float a = __fmaf_rn(np0, G, p0);
            a       = __fmaf_rn(np1, S, a);
            float c = __fmaf_rn(p2, G, np4);
            float b = __fmaf_rn(np3, W, c);
            float d = __fmaf_rn(p5, S, np7);
            float e = __fmul_rn(W, d);
            float nS = __fmaf_rn(b, S, S);
            float nW = __fmaf_rn(e, W, W);
            float nG = __fmaf_rn(a, G, G);
            W = nW; S = nS; G = nG;
            traj[j] = make_float4(B, W, S, G);
        }

        // ---- Phase 2: mask == 1 hot loop (12 fma-port + 2 alu ops) ----
        int j = j0;
        while (j < num_steps) {
            const int end = min((((j >> CHUNK_LOG2) + 1) << CHUNK_LOG2),
                                num_steps);
            #pragma unroll 64
            for (; j < end; ++j) {
                float a = __fmaf_rn(np0, G, p0);     // p0 - p0*G
                a       = __fmaf_rn(np1, S, a);      //   - p1*S
                float t = __fadd_rn(W, B);           // W + B   (alu pipe)
                float c = __fmaf_rn(p2, G, np4);     // p2*G - p4
                float b = __fmaf_rn(np3, t, c);      //   - p3*(W+B)
                float d = __fmaf_rn(p5, S, np7);     // p5*S - p7
                d       = __fmaf_rn(np6, B, d);      //   - p6*B
                float e = __fmul_rn(W, d);           // W*(...)
                float f = __fadd_rn(S, W);           // S + W   (alu pipe)
                float g = __fmaf_rn(p8, f, np9);     // p8*(S+W) - p9
                float nB = __fmaf_rn(g, B, B);
                float nW = __fmaf_rn(e, W, W);
                float nS = __fmaf_rn(b, S, S);
                float nG = __fmaf_rn(a, G, G);
                B = nB; W = nW; S = nS; G = nG;
                traj[j] = make_float4(B, W, S, G);   // STS.128 (imm offset)
            }
            __threadfence_block();
            s_progress = end;
        }
        __threadfence_block();
        s_progress = num_steps;  // covers j0 == num_steps
    } else if (wid != 4 && tid >= 32) {
        // ------- consumers: warps 1,2,3,5,6,7 (SMSP 0 kept clear) --------
        const int ct  = (wid < 4) ? (tid - 32) : (tid - 64);  // 0..191
        const int ncs = 192;
        const float* tf = (const float*)traj;       // flat smem floats
        float4* o4 = (float4*)out;

        const int total_f  = num_steps * 5;
        const int total_f4 = total_f >> 2;
        const int n_chunks = (num_steps + CHUNK - 1) >> CHUNK_LOG2;
        const int f4_per_chunk = (CHUNK * 5) >> 2;  // 640

        for (int k = 0; k < n_chunks; ++k) {
            const int rows_done = min((k + 1) << CHUNK_LOG2, num_steps);
            while (s_progress < rows_done) __nanosleep(256);
            __threadfence_block();  // acquire: traj data before flag

            const int m0 = k * f4_per_chunk;
            const int m1 = min(m0 + f4_per_chunk, total_f4);
            for (int m = m0 + ct; m < m1; m += ncs) {
                const int n = m << 2;
                float v[4];
                #pragma unroll
                for (int e = 0; e < 4; ++e) {
                    const int ne = n + e;
                    const int r  = ne / 5;
                    const int c  = ne - r * 5;
                    v[e] = (c == 4) ? iv : tf[(r << 2) + c];
                }
                o4[m] = make_float4(v[0], v[1], v[2], v[3]);  // STG.128
            }
        }
        // scalar tail if num_steps*5 % 4 != 0 (not hit at 8192, kept general)
        if (ct == 0) {
            for (int ne = total_f4 << 2; ne < total_f; ++ne) {
                const int r = ne / 5;
                const int c = ne - r * 5;
                out[ne] = (c == 4) ? iv : tf[(r << 2) + c];
            }
        }
    }
    // warp 0 lanes 1..31 and all of warp 4: fall through and exit,
    // leaving SMSP 0's issue slots to the producer.
}

extern "C" void kernel_launch(void* const* d_in, const int* in_sizes, int n_in,
                              void* d_out, int out_size) {
    const float* y0     = (const float*)d_in[0];
    const float* params = (const float*)d_in[1];
    const int num_steps = out_size / 5;

    const size_t smem = (size_t)num_steps * sizeof(float4);
    cudaFuncSetAttribute(bwsg_ode_kernel,
                         cudaFuncAttributeMaxDynamicSharedMemorySize,
                         (int)smem);
    bwsg_ode_kernel<<<1, 256, smem>>>(y0, params, (float*)d_out, num_steps);
}

// round 14
// speedup vs baseline: 1.1958x; 1.0111x over previous
#include <cuda_runtime.h>

// BWSGODE: 8192-step serial scalar ODE — issue-bound single-thread loop.
//
// v14 = v13 (best, 102.4us) with unroll 64 -> 128 and CHUNK 512 -> 1024.
// Model (locked r12/r13): 12 fma-port ops x rt2 = 24 cyc/iter floor (the
// two FADDs ride the alu pipe); measured 24.3. Remaining residue is
// taken-BRA + chunk bookkeeping; this halves both (BRA share 0.16 -> 0.08
// cyc/iter, publishes 16 -> 8). Risk knob: body ~30KB SASS vs 32KB L1.5
// I$ — if it spills, +0.032 cyc/instr erases the gain and v13 stands.
// Structure (locked since r7): thread 0 produces into shared traj and
// publishes chunks via fence + volatile store; warps 1,2,3,5,6,7 stream
// chunks to global as STG.128; warp 4 exits so SMSP 0 belongs to the
// producer alone (hi-wid-first arbiter).

#define CHUNK_LOG2 10
#define CHUNK (1 << CHUNK_LOG2)

__shared__ volatile int s_progress;

__global__ void __launch_bounds__(256, 1)
bwsg_ode_kernel(const float* __restrict__ y0,
                const float* __restrict__ p,
                float* __restrict__ out,
                int num_steps) {
    extern __shared__ float4 traj[];  // num_steps entries (128 KB @ 8192)

    const int tid = threadIdx.x;
    const int wid = tid >> 5;
    if (tid == 0) s_progress = 0;
    __syncthreads();  // the ONLY block-wide sync; everything after is P/C.

    const float iv = __ldg(&y0[4]);

    if (tid == 0) {
        // ---------------- producer: the serial recurrence ----------------
        float B = __ldg(&y0[0]);
        float W = __ldg(&y0[1]);
        float S = __ldg(&y0[2]);
        float G = __ldg(&y0[3]);

        const float p0 = p[0], p2 = p[2], p5 = p[5], p8 = p[8];
        const float np1 = -p[1], np3 = -p[3], np4 = -p[4];
        const float np6 = -p[6], np7 = -p[7], np9 = -p[9];
        const float np0 = -p0;

        const float fi  = (iv != 0.0f) ? 1.0f : 0.0f;
        const float thr = __fsub_rn(__fadd_rn(5.0f, iv), 1.0f);

        // First integer step with mask==1 (j >= thr <=> j >= ceil(thr) for
        // integer j; fp compare of exact integers is exact).
        int j0 = 1;
        if (fi != 0.0f) {
            float ct = ceilf(thr);
            if (ct > 1.0f) {
                j0 = (ct >= (float)num_steps) ? num_steps : (int)ct;
            }
        }

        traj[0] = make_float4(B, W, S, G);

        // ---- Phase 1: mask == 0 (interventional only), B frozen ----
        for (int j = 1; j < j0; ++j) {
            float a = __fmaf_rn(np0, G, p0);
            a       = __fmaf_rn(np1, S, a);
            float c = __fmaf_rn(p2, G, np4);
            float b = __fmaf_rn(np3, W, c);
            float d = __fmaf_rn(p5, S, np7);
            float e = __fmul_rn(W, d);
            float nS = __fmaf_rn(b, S, S);
            float nW = __fmaf_rn(e, W, W);
            float nG = __fmaf_rn(a, G, G);
            W = nW; S = nS; G = nG;
            traj[j] = make_float4(B, W, S, G);
        }

        // ---- Phase 2: mask == 1 hot loop (12 fma-port + 2 alu ops) ----
        int j = j0;
        while (j < num_steps) {
            const int end = min((((j >> CHUNK_LOG2) + 1) << CHUNK_LOG2),
                                num_steps);
            #pragma unroll 128
            for (; j < end; ++j) {
                float a = __fmaf_rn(np0, G, p0);     // p0 - p0*G
                a       = __fmaf_rn(np1, S, a);      //   - p1*S
                float t = __fadd_rn(W, B);           // W + B   (alu pipe)
                float c = __fmaf_rn(p2, G, np4);     // p2*G - p4
                float b = __fmaf_rn(np3, t, c);      //   - p3*(W+B)
                float d = __fmaf_rn(p5, S, np7);     // p5*S - p7
                d       = __fmaf_rn(np6, B, d);      //   - p6*B
                float e = __fmul_rn(W, d);           // W*(...)
                float f = __fadd_rn(S, W);           // S + W   (alu pipe)
                float g = __fmaf_rn(p8, f, np9);     // p8*(S+W) - p9
                float nB = __fmaf_rn(g, B, B);
                float nW = __fmaf_rn(e, W, W);
                float nS = __fmaf_rn(b, S, S);
                float nG = __fmaf_rn(a, G, G);
                B = nB; W = nW; S = nS; G = nG;
                traj[j] = make_float4(B, W, S, G);   // STS.128 (imm offset)
            }
            __threadfence_block();
            s_progress = end;
        }
        __threadfence_block();
        s_progress = num_steps;  // covers j0 == num_steps
    } else if (wid != 4 && tid >= 32) {
        // ------- consumers: warps 1,2,3,5,6,7 (SMSP 0 kept clear) --------
        const int ct  = (wid < 4) ? (tid - 32) : (tid - 64);  // 0..191
        const int ncs = 192;
        const float* tf = (const float*)traj;       // flat smem floats
        float4* o4 = (float4*)out;

        const int total_f  = num_steps * 5;
        const int total_f4 = total_f >> 2;
        const int n_chunks = (num_steps + CHUNK - 1) >> CHUNK_LOG2;
        const int f4_per_chunk = (CHUNK * 5) >> 2;  // 1280

        for (int k = 0; k < n_chunks; ++k) {
            const int rows_done = min((k + 1) << CHUNK_LOG2, num_steps);
            while (s_progress < rows_done) __nanosleep(256);
            __threadfence_block();  // acquire: traj data before flag

            const int m0 = k * f4_per_chunk;
            const int m1 = min(m0 + f4_per_chunk, total_f4);
            for (int m = m0 + ct; m < m1; m += ncs) {
                const int n = m << 2;
                float v[4];
                #pragma unroll
                for (int e = 0; e < 4; ++e) {
                    const int ne = n + e;
                    const int r  = ne / 5;
                    const int c  = ne - r * 5;
                    v[e] = (c == 4) ? iv : tf[(r << 2) + c];
                }
                o4[m] = make_float4(v[0], v[1], v[2], v[3]);  // STG.128
            }
        }
        // scalar tail if num_steps*5 % 4 != 0 (not hit at 8192, kept general)
        if (ct == 0) {
            for (int ne = total_f4 << 2; ne < total_f; ++ne) {
                const int r = ne / 5;
                const int c = ne - r * 5;
                out[ne] = (c == 4) ? iv : tf[(r << 2) + c];
            }
        }
    }
    // warp 0 lanes 1..31 and all of warp 4: fall through and exit,
    // leaving SMSP 0's issue slots to the producer.
}

extern "C" void kernel_launch(void* const* d_in, const int* in_sizes, int n_in,
                              void* d_out, int out_size) {
    const float* y0     = (const float*)d_in[0];
    const float* params = (const float*)d_in[1];
    const int num_steps = out_size / 5;

    const size_t smem = (size_t)num_steps * sizeof(float4);
    cudaFuncSetAttribute(bwsg_ode_kernel,
                         cudaFuncAttributeMaxDynamicSharedMemorySize,
                         (int)smem);
    bwsg_ode_kernel<<<1, 256, smem>>>(y0, params, (float*)d_out, num_steps);
}